// round 16
// baseline (speedup 1.0000x reference)
#include <cuda_runtime.h>
#include <cuda_fp16.h>
#include <math.h>

#define NT 2000
#define NPT 255
#define NC 16
#define NM 32
#define NG 16
#define PGRID 592                     // persistent grid: 4 CTAs/SM x 148 SMs

// dynamic shared layout (bytes)
//   [0, 16384)      : sWh — 32 pairsum slots x 256 halfs ([slot][g][c])
//                     (fp32 A staging scratch overlays this region)
//   [16384, 32768)  : sPBh — normalized leaf beta Pi*B/nu, [m][g][c] half
//   [32768, 49152)  : sEh  — emission B/nu, [m][g][c] half
//   [49152, 51200)  : sNuL — log2 nu per (m,g), fp32
#define PB_BYTE_OFF  16384
#define E_BYTE_OFF   32768
#define NUL_BYTE_OFF 49152
#define DYN_BYTES    51200

__device__ float g_smA[NC*NC*NG];     // softmaxed A, [p][c][g]
__device__ float g_smBf[NM*NG*NC];    // softmaxed B, [m][g][c] (prologue only)
__device__ float g_smPi[NC*NG];       // softmaxed Pi, [c][g]
__device__ float g_PiBn[NM*NG*NC];    // normalized leaf beta, [m][g][c]
__device__ float g_Enu[NM*NG*NC];     // emission B/nu, [m][g][c]
__device__ float g_nuLog[NM*NG];      // log2 nu per (m,g)

__device__ __forceinline__ __half2 u2h(unsigned u) { return *(__half2*)&u; }
__device__ __forceinline__ unsigned h2u(__half2 h) { return *(unsigned*)&h; }

// ---------------------------------------------------------------------------
// Prologue: softmaxes + PiBn + E + log2 nu. 1 block, 256 threads.
// ---------------------------------------------------------------------------
__global__ void htmm_softmax_kernel(const float* __restrict__ A,
                                    const float* __restrict__ B,
                                    const float* __restrict__ Pi) {
    int tid = threadIdx.x;
    int c = tid >> 4;
    int g = tid & 15;
    {   // A: softmax over p for each (c,g)
        float mx = -1e30f;
        #pragma unroll
        for (int p = 0; p < NC; p++) mx = fmaxf(mx, A[p*NC*NG + c*NG + g]);
        float e[NC]; float s = 0.f;
        #pragma unroll
        for (int p = 0; p < NC; p++) { e[p] = expf(A[p*NC*NG + c*NG + g] - mx); s += e[p]; }
        float rs = 1.f / s;
        #pragma unroll
        for (int p = 0; p < NC; p++) g_smA[p*NC*NG + c*NG + g] = e[p] * rs;
    }
    {   // B: softmax over m for each (c,g); store [m][g][c]
        float mx = -1e30f;
        #pragma unroll
        for (int m = 0; m < NM; m++) mx = fmaxf(mx, B[c*NM*NG + m*NG + g]);
        float s = 0.f;
        #pragma unroll
        for (int m = 0; m < NM; m++) s += expf(B[c*NM*NG + m*NG + g] - mx);
        float rs = 1.f / s;
        #pragma unroll
        for (int m = 0; m < NM; m++)
            g_smBf[m*NG*NC + g*NC + c] = expf(B[c*NM*NG + m*NG + g] - mx) * rs;
    }
    if (tid < NG) {   // Pi: softmax over c for each g
        int gg = tid;
        float mx = -1e30f;
        #pragma unroll
        for (int cc = 0; cc < NC; cc++) mx = fmaxf(mx, Pi[cc*NG + gg]);
        float s = 0.f;
        #pragma unroll
        for (int cc = 0; cc < NC; cc++) s += expf(Pi[cc*NG + gg] - mx);
        float rs = 1.f / s;
        #pragma unroll
        for (int cc = 0; cc < NC; cc++)
            g_smPi[cc*NG + gg] = expf(Pi[cc*NG + gg] - mx) * rs;
    }
    __syncthreads();
    // per (m,g): v = Pi*B; nu = sum v; PiBn = v/nu; E = B/nu; log2 nu
    for (int i = tid; i < NM*NG; i += 256) {
        int m = i >> 4, gg = i & 15;
        float v[NC]; float nu = 0.f;
        #pragma unroll
        for (int cc = 0; cc < NC; cc++) {
            v[cc] = g_smPi[cc*NG + gg] * g_smBf[m*NG*NC + gg*NC + cc];
            nu += v[cc];
        }
        float rnu = 1.f / nu;
        #pragma unroll
        for (int cc = 0; cc < NC; cc++) {
            g_PiBn[m*NG*NC + gg*NC + cc] = v[cc] * rnu;
            g_Enu[m*NG*NC + gg*NC + cc]  = g_smBf[m*NG*NC + gg*NC + cc] * rnu;
        }
        g_nuLog[i] = log2f(nu);
    }
}

// ---------------------------------------------------------------------------
// Main kernel: PERSISTENT, SUBTREE-DECOMPOSED, HALF2 hot path (R15 body,
// unchanged). R16 single delta: 4 CTAs/SM (64-reg cap) + grid 592.
// pblk = tid&3 (states p = 4*pblk..+3), g = (tid>>2)&15, ng = tid>>6.
// ---------------------------------------------------------------------------
__global__ void __launch_bounds__(256, 4)
htmm_upward_kernel(const int* __restrict__ x, float* __restrict__ out) {
    extern __shared__ __align__(16) unsigned char smraw[];
    __half* sWh  = (__half*)smraw;                    // 32 slots x 256 halfs
    __half* sPBh = (__half*)(smraw + PB_BYTE_OFF);    // [m][g][c] half
    __half* sEh  = (__half*)(smraw + E_BYTE_OFF);     // [m][g][c] half
    float*  sNuL = (float*)(smraw + NUL_BYTE_OFF);    // [m*NG+g]
    float*  Ascr = (float*)smraw;                     // fp32 A staging overlay
    __shared__ int   sx[NPT];
    __shared__ float sacc[256];

    const int tid  = threadIdx.x;
    const int pblk = tid & 3;
    const int g    = (tid >> 2) & 15;
    const int ng   = tid >> 6;
    const int rowoff = g*16;                          // half offset within slot
    const int sbase  = ng*8;                          // this subtree's slot base

    // ---- stage tables ONCE ----
    for (int i = tid; i < NC*NC*NG; i += 256) Ascr[i] = g_smA[i];
    for (int i = tid; i < NM*NG*NC; i += 256) {
        sPBh[i] = __float2half_rn(g_PiBn[i]);
        sEh[i]  = __float2half_rn(g_Enu[i]);
    }
    for (int i = tid; i < NM*NG; i += 256)    sNuL[i] = g_nuLog[i];
    __syncthreads();

    // A rows packed as half2 along c pairs: 32 regs total
    unsigned A2h[4][8];
    #pragma unroll
    for (int ip = 0; ip < 4; ip++) {
        int p = 4*pblk + ip;
        #pragma unroll
        for (int c2 = 0; c2 < 8; c2++)
            A2h[ip][c2] = h2u(__floats2half2_rn(Ascr[p*256 + (2*c2)*16 + g],
                                                Ascr[p*256 + (2*c2+1)*16 + g]));
    }
    __syncthreads();   // Ascr scratch (= sWh region) may now be overwritten

    // ---- persistent tree loop ----
    for (int tree = blockIdx.x; tree < NT; tree += PGRID) {
        __syncthreads();   // previous tree fully done
        for (int i = tid; i < NPT; i += 256) sx[i] = x[tree*NPT + i];
        __syncthreads();

        float accll = 0.f;   // log2 units

        // per-node tail: half-domain horizontal combine, 2 converts total
        #define NODE_TAIL(MU, A0, A1, A2_, A3_, BV0, BV1, BV2, BV3, SS)       \
            __half2 t01 = __hadd2(__lows2half2(A0, A1), __highs2half2(A0, A1)); \
            __half2 t23 = __hadd2(__lows2half2(A2_, A3_), __highs2half2(A2_, A3_)); \
            const uint2 eu = *(const uint2*)(sEh + (MU)*256 + rowoff + 4*pblk); \
            float2 f01 = __half22float2(__hmul2(u2h(eu.x), t01));             \
            float2 f23 = __half22float2(__hmul2(u2h(eu.y), t23));             \
            float BV0 = f01.x, BV1 = f01.y, BV2 = f23.x, BV3 = f23.y;         \
            float SS = (BV0 + BV1) + (BV2 + BV3);                             \
            SS += __shfl_xor_sync(0xffffffffu, SS, 1);                        \
            SS += __shfl_xor_sync(0xffffffffu, SS, 2);

        // ====== SUBTREE ng: levels 6..2, barrier-free (quad-local rows) ======

        // ---- Level 6 (leaves fused): 8 local parents k -> slots sbase+k ----
        for (int k = 0; k < 8; k++) {
            float wo0 = 0.f, wo1 = 0.f, wo2 = 0.f, wo3 = 0.f;
            #pragma unroll
            for (int sel = 0; sel < 2; sel++) {
                const int j  = 2*k + sel;                   // local L6 node 0..15
                const int lf = 127 + 32*ng + 2*j;
                const int m0 = sx[lf], m1 = sx[lf + 1];
                const int mu = sx[63 + 16*ng + j];
                const uint4* b0 = (const uint4*)(sPBh + m0*256 + rowoff);
                const uint4* b1 = (const uint4*)(sPBh + m1*256 + rowoff);
                uint4 qa0 = b0[0], qa1 = b0[1];
                uint4 qb0 = b1[0], qb1 = b1[1];
                unsigned ua[8] = {qa0.x,qa0.y,qa0.z,qa0.w, qa1.x,qa1.y,qa1.z,qa1.w};
                unsigned ub[8] = {qb0.x,qb0.y,qb0.z,qb0.w, qb1.x,qb1.y,qb1.z,qb1.w};
                __half2 a0 = __float2half2_rn(0.f), a1 = a0, a2 = a0, a3 = a0;
                #pragma unroll
                for (int c2 = 0; c2 < 8; c2++) {
                    __half2 w2 = __hadd2(u2h(ua[c2]), u2h(ub[c2]));  // leaf pairsum
                    a0 = __hfma2(u2h(A2h[0][c2]), w2, a0);
                    a1 = __hfma2(u2h(A2h[1][c2]), w2, a1);
                    a2 = __hfma2(u2h(A2h[2][c2]), w2, a2);
                    a3 = __hfma2(u2h(A2h[3][c2]), w2, a3);
                }
                accll += 0.25f * (sNuL[m0*NG + g] + sNuL[m1*NG + g]);  // leaf lls

                NODE_TAIL(mu, a0, a1, a2, a3, bv0, bv1, bv2, bv3, s)
                float rs = __fdividef(1.f, s);
                wo0 += bv0*rs; wo1 += bv1*rs; wo2 += bv2*rs; wo3 += bv3*rs;
                accll += 0.25f * (__log2f(s) + sNuL[mu*NG + g]);
            }
            uint2 st;
            st.x = h2u(__floats2half2_rn(wo0, wo1));
            st.y = h2u(__floats2half2_rn(wo2, wo3));
            *(uint2*)(sWh + (sbase + k)*256 + rowoff + 4*pblk) = st;
        }
        __syncwarp();

        // ---- Levels 5..3 (in-place, stride doubling, local to subtree) ----
        #pragma unroll 1
        for (int l = 5; l >= 3; l--) {
            const int nParL = 1 << (l - 3);          // 4, 2, 1
            const int st    = 1 << (5 - l);          // 1, 2, 4
            const int nbase = (1 << l) - 1 + (1 << (l - 2))*ng;
            for (int k = 0; k < nParL; k++) {
                float wo0 = 0.f, wo1 = 0.f, wo2 = 0.f, wo3 = 0.f;
                #pragma unroll
                for (int sel = 0; sel < 2; sel++) {
                    const int j = 2*k + sel;
                    const int mu = sx[nbase + j];
                    const uint4* wp = (const uint4*)(sWh + (sbase + j*st)*256 + rowoff);
                    uint4 q0 = wp[0], q1 = wp[1];
                    unsigned uw[8] = {q0.x,q0.y,q0.z,q0.w, q1.x,q1.y,q1.z,q1.w};
                    __half2 a0 = __float2half2_rn(0.f), a1 = a0, a2 = a0, a3 = a0;
                    #pragma unroll
                    for (int c2 = 0; c2 < 8; c2++) {
                        __half2 w2 = u2h(uw[c2]);    // pre-summed sibling pair
                        a0 = __hfma2(u2h(A2h[0][c2]), w2, a0);
                        a1 = __hfma2(u2h(A2h[1][c2]), w2, a1);
                        a2 = __hfma2(u2h(A2h[2][c2]), w2, a2);
                        a3 = __hfma2(u2h(A2h[3][c2]), w2, a3);
                    }
                    NODE_TAIL(mu, a0, a1, a2, a3, bv0, bv1, bv2, bv3, s)
                    // true nu = s*nu(mu)/2; cancels in normalization;
                    // -1 folded at end, +log2 nu(mu) here
                    float rs = __fdividef(1.f, s);
                    wo0 += bv0*rs; wo1 += bv1*rs; wo2 += bv2*rs; wo3 += bv3*rs;
                    accll += 0.25f * (__log2f(s) + sNuL[mu*NG + g]);
                }
                uint2 stv;
                stv.x = h2u(__floats2half2_rn(wo0, wo1));
                stv.y = h2u(__floats2half2_rn(wo2, wo3));
                *(uint2*)(sWh + (sbase + 2*k*st)*256 + rowoff + 4*pblk) = stv;
            }
            __syncwarp();
        }

        // ---- L2 node (one per subtree): normalized beta -> slot sbase+1 ----
        {
            const int mu = sx[3 + ng];
            const uint4* wp = (const uint4*)(sWh + sbase*256 + rowoff);  // L3 pairsum
            uint4 q0 = wp[0], q1 = wp[1];
            unsigned uw[8] = {q0.x,q0.y,q0.z,q0.w, q1.x,q1.y,q1.z,q1.w};
            __half2 a0 = __float2half2_rn(0.f), a1 = a0, a2 = a0, a3 = a0;
            #pragma unroll
            for (int c2 = 0; c2 < 8; c2++) {
                __half2 w2 = u2h(uw[c2]);
                a0 = __hfma2(u2h(A2h[0][c2]), w2, a0);
                a1 = __hfma2(u2h(A2h[1][c2]), w2, a1);
                a2 = __hfma2(u2h(A2h[2][c2]), w2, a2);
                a3 = __hfma2(u2h(A2h[3][c2]), w2, a3);
            }
            NODE_TAIL(mu, a0, a1, a2, a3, bv0, bv1, bv2, bv3, s)
            float rs = __fdividef(1.f, s);
            uint2 stv;
            stv.x = h2u(__floats2half2_rn(bv0*rs, bv1*rs));
            stv.y = h2u(__floats2half2_rn(bv2*rs, bv3*rs));
            *(uint2*)(sWh + (sbase + 1)*256 + rowoff + 4*pblk) = stv;
            accll += 0.25f * (__log2f(s) + sNuL[mu*NG + g]);
        }

        __syncthreads();   // L2 betas of all 4 subtrees visible

        // ---- L1 + root: ng0 only ----
        if (ng == 0) {
            float wo0 = 0.f, wo1 = 0.f, wo2 = 0.f, wo3 = 0.f;
            #pragma unroll
            for (int sel = 0; sel < 2; sel++) {
                const int mu = sx[1 + sel];
                const uint4* r0 = (const uint4*)(sWh + (2*sel*8 + 1)*256 + rowoff);
                const uint4* r1 = (const uint4*)(sWh + ((2*sel+1)*8 + 1)*256 + rowoff);
                uint4 qa0 = r0[0], qa1 = r0[1];
                uint4 qb0 = r1[0], qb1 = r1[1];
                unsigned ua[8] = {qa0.x,qa0.y,qa0.z,qa0.w, qa1.x,qa1.y,qa1.z,qa1.w};
                unsigned ub[8] = {qb0.x,qb0.y,qb0.z,qb0.w, qb1.x,qb1.y,qb1.z,qb1.w};
                __half2 a0 = __float2half2_rn(0.f), a1 = a0, a2 = a0, a3 = a0;
                #pragma unroll
                for (int c2 = 0; c2 < 8; c2++) {
                    __half2 w2 = __hadd2(u2h(ua[c2]), u2h(ub[c2]));  // L2 pairsum
                    a0 = __hfma2(u2h(A2h[0][c2]), w2, a0);
                    a1 = __hfma2(u2h(A2h[1][c2]), w2, a1);
                    a2 = __hfma2(u2h(A2h[2][c2]), w2, a2);
                    a3 = __hfma2(u2h(A2h[3][c2]), w2, a3);
                }
                NODE_TAIL(mu, a0, a1, a2, a3, bv0, bv1, bv2, bv3, s)
                float rs = __fdividef(1.f, s);
                wo0 += bv0*rs; wo1 += bv1*rs; wo2 += bv2*rs; wo3 += bv3*rs;
                accll += 0.25f * (__log2f(s) + sNuL[mu*NG + g]);
            }
            uint2 stv;
            stv.x = h2u(__floats2half2_rn(wo0, wo1));
            stv.y = h2u(__floats2half2_rn(wo2, wo3));
            *(uint2*)(sWh + 2*256 + rowoff + 4*pblk) = stv;
            __syncwarp();
            const int mu = sx[0];
            const uint4* wp = (const uint4*)(sWh + 2*256 + rowoff);
            uint4 q0 = wp[0], q1 = wp[1];
            unsigned uw[8] = {q0.x,q0.y,q0.z,q0.w, q1.x,q1.y,q1.z,q1.w};
            __half2 a0 = __float2half2_rn(0.f), a1 = a0, a2 = a0, a3 = a0;
            #pragma unroll
            for (int c2 = 0; c2 < 8; c2++) {
                __half2 w2 = u2h(uw[c2]);
                a0 = __hfma2(u2h(A2h[0][c2]), w2, a0);
                a1 = __hfma2(u2h(A2h[1][c2]), w2, a1);
                a2 = __hfma2(u2h(A2h[2][c2]), w2, a2);
                a3 = __hfma2(u2h(A2h[3][c2]), w2, a3);
            }
            NODE_TAIL(mu, a0, a1, a2, a3, bv0, bv1, bv2, bv3, s)
            (void)bv0; (void)bv1; (void)bv2; (void)bv3;
            accll += 0.25f * (__log2f(s) + sNuL[mu*NG + g]);
        }
        #undef NODE_TAIL

        // ---- Deterministic per-g reduction over the 16 threads sharing g ----
        sacc[tid] = accll;
        __syncthreads();
        if (tid < NG) {
            float s = 0.f;
            #pragma unroll
            for (int kk = 0; kk < 16; kk++)
                s += sacc[(kk >> 2)*64 + tid*4 + (kk & 3)];
            // 127 internal nodes owe -1 each in log2 (folded BF=2 mean); to ln
            out[tree*NG + tid] = 0.69314718055994530942f * (s - 127.0f);
        }
    }
}

// ---------------------------------------------------------------------------
extern "C" void kernel_launch(void* const* d_in, const int* in_sizes, int n_in,
                              void* d_out, int out_size) {
    const float* A  = (const float*)d_in[0];
    const float* B  = (const float*)d_in[1];
    const float* Pi = (const float*)d_in[2];
    const int*   x  = (const int*)  d_in[3];
    float* out = (float*)d_out;

    cudaFuncSetAttribute(htmm_upward_kernel,
                         cudaFuncAttributeMaxDynamicSharedMemorySize, DYN_BYTES);

    htmm_softmax_kernel<<<1, 256>>>(A, B, Pi);
    htmm_upward_kernel<<<PGRID, 256, DYN_BYTES>>>(x, out);
}

// round 17
// speedup vs baseline: 1.0481x; 1.0481x over previous
#include <cuda_runtime.h>
#include <cuda_fp16.h>
#include <math.h>

#define NT 2000
#define NPT 255
#define NC 16
#define NM 32
#define NG 16
#define PGRID 444                     // persistent grid: 3 CTAs/SM x 148 SMs

// dynamic shared layout (bytes)
//   [0, 16384)      : sWh — 32 pairsum slots x 256 halfs ([slot][g][c])
//                     (fp32 A staging scratch overlays this region)
//   [16384, 32768)  : sPBh — normalized leaf beta Pi*B/nu, [m][g][c] half
//   [32768, 49152)  : sEh  — emission B/nu, [m][g][c] half
//   [49152, 51200)  : sNuL — log2 nu per (m,g), fp32
#define PB_BYTE_OFF  16384
#define E_BYTE_OFF   32768
#define NUL_BYTE_OFF 49152
#define DYN_BYTES    51200

__device__ float g_smA[NC*NC*NG];     // softmaxed A, [p][c][g]
__device__ float g_smBf[NM*NG*NC];    // softmaxed B, [m][g][c] (prologue only)
__device__ float g_smPi[NC*NG];       // softmaxed Pi, [c][g]
__device__ float g_PiBn[NM*NG*NC];    // normalized leaf beta, [m][g][c]
__device__ float g_Enu[NM*NG*NC];     // emission B/nu, [m][g][c]
__device__ float g_nuLog[NM*NG];      // log2 nu per (m,g)
__device__ int   g_tree_ctr;          // dynamic work counter (reset in prologue)

__device__ __forceinline__ __half2 u2h(unsigned u) { return *(__half2*)&u; }
__device__ __forceinline__ unsigned h2u(__half2 h) { return *(unsigned*)&h; }

// ---------------------------------------------------------------------------
// Prologue: softmaxes + PiBn + E + log2 nu; resets the work counter.
// 1 block, 256 threads.
// ---------------------------------------------------------------------------
__global__ void htmm_softmax_kernel(const float* __restrict__ A,
                                    const float* __restrict__ B,
                                    const float* __restrict__ Pi) {
    int tid = threadIdx.x;
    if (tid == 0) g_tree_ctr = 0;     // reset work-stealing counter each replay
    int c = tid >> 4;
    int g = tid & 15;
    {   // A: softmax over p for each (c,g)
        float mx = -1e30f;
        #pragma unroll
        for (int p = 0; p < NC; p++) mx = fmaxf(mx, A[p*NC*NG + c*NG + g]);
        float e[NC]; float s = 0.f;
        #pragma unroll
        for (int p = 0; p < NC; p++) { e[p] = expf(A[p*NC*NG + c*NG + g] - mx); s += e[p]; }
        float rs = 1.f / s;
        #pragma unroll
        for (int p = 0; p < NC; p++) g_smA[p*NC*NG + c*NG + g] = e[p] * rs;
    }
    {   // B: softmax over m for each (c,g); store [m][g][c]
        float mx = -1e30f;
        #pragma unroll
        for (int m = 0; m < NM; m++) mx = fmaxf(mx, B[c*NM*NG + m*NG + g]);
        float s = 0.f;
        #pragma unroll
        for (int m = 0; m < NM; m++) s += expf(B[c*NM*NG + m*NG + g] - mx);
        float rs = 1.f / s;
        #pragma unroll
        for (int m = 0; m < NM; m++)
            g_smBf[m*NG*NC + g*NC + c] = expf(B[c*NM*NG + m*NG + g] - mx) * rs;
    }
    if (tid < NG) {   // Pi: softmax over c for each g
        int gg = tid;
        float mx = -1e30f;
        #pragma unroll
        for (int cc = 0; cc < NC; cc++) mx = fmaxf(mx, Pi[cc*NG + gg]);
        float s = 0.f;
        #pragma unroll
        for (int cc = 0; cc < NC; cc++) s += expf(Pi[cc*NG + gg] - mx);
        float rs = 1.f / s;
        #pragma unroll
        for (int cc = 0; cc < NC; cc++)
            g_smPi[cc*NG + gg] = expf(Pi[cc*NG + gg] - mx) * rs;
    }
    __syncthreads();
    // per (m,g): v = Pi*B; nu = sum v; PiBn = v/nu; E = B/nu; log2 nu
    for (int i = tid; i < NM*NG; i += 256) {
        int m = i >> 4, gg = i & 15;
        float v[NC]; float nu = 0.f;
        #pragma unroll
        for (int cc = 0; cc < NC; cc++) {
            v[cc] = g_smPi[cc*NG + gg] * g_smBf[m*NG*NC + gg*NC + cc];
            nu += v[cc];
        }
        float rnu = 1.f / nu;
        #pragma unroll
        for (int cc = 0; cc < NC; cc++) {
            g_PiBn[m*NG*NC + gg*NC + cc] = v[cc] * rnu;
            g_Enu[m*NG*NC + gg*NC + cc]  = g_smBf[m*NG*NC + gg*NC + cc] * rnu;
        }
        g_nuLog[i] = log2f(nu);
    }
}

// ---------------------------------------------------------------------------
// Main kernel: PERSISTENT, SUBTREE-DECOMPOSED, HALF2 hot path (R15 body,
// unchanged). R17 single delta: trees claimed via global atomicAdd
// (work-stealing) instead of static stride — removes the 5-vs-4.5 tree
// quantization tail and absorbs per-SM spread. Output remains deterministic
// (each tree's computation and output rows are assignment-independent).
// pblk = tid&3 (states p = 4*pblk..+3), g = (tid>>2)&15, ng = tid>>6.
// ---------------------------------------------------------------------------
__global__ void __launch_bounds__(256, 3)
htmm_upward_kernel(const int* __restrict__ x, float* __restrict__ out) {
    extern __shared__ __align__(16) unsigned char smraw[];
    __half* sWh  = (__half*)smraw;                    // 32 slots x 256 halfs
    __half* sPBh = (__half*)(smraw + PB_BYTE_OFF);    // [m][g][c] half
    __half* sEh  = (__half*)(smraw + E_BYTE_OFF);     // [m][g][c] half
    float*  sNuL = (float*)(smraw + NUL_BYTE_OFF);    // [m*NG+g]
    float*  Ascr = (float*)smraw;                     // fp32 A staging overlay
    __shared__ int   sx[NPT];
    __shared__ float sacc[256];
    __shared__ int   sTree;

    const int tid  = threadIdx.x;
    const int pblk = tid & 3;
    const int g    = (tid >> 2) & 15;
    const int ng   = tid >> 6;
    const int rowoff = g*16;                          // half offset within slot
    const int sbase  = ng*8;                          // this subtree's slot base

    // ---- stage tables ONCE ----
    for (int i = tid; i < NC*NC*NG; i += 256) Ascr[i] = g_smA[i];
    for (int i = tid; i < NM*NG*NC; i += 256) {
        sPBh[i] = __float2half_rn(g_PiBn[i]);
        sEh[i]  = __float2half_rn(g_Enu[i]);
    }
    for (int i = tid; i < NM*NG; i += 256)    sNuL[i] = g_nuLog[i];
    __syncthreads();

    // A rows packed as half2 along c pairs: 32 regs total
    unsigned A2h[4][8];
    #pragma unroll
    for (int ip = 0; ip < 4; ip++) {
        int p = 4*pblk + ip;
        #pragma unroll
        for (int c2 = 0; c2 < 8; c2++)
            A2h[ip][c2] = h2u(__floats2half2_rn(Ascr[p*256 + (2*c2)*16 + g],
                                                Ascr[p*256 + (2*c2+1)*16 + g]));
    }
    __syncthreads();   // Ascr scratch (= sWh region) may now be overwritten

    // ---- persistent work-stealing tree loop ----
    for (;;) {
        __syncthreads();   // previous tree fully done (slots, sacc, sTree free)
        if (tid == 0) sTree = atomicAdd(&g_tree_ctr, 1);
        __syncthreads();
        const int tree = sTree;
        if (tree >= NT) break;
        for (int i = tid; i < NPT; i += 256) sx[i] = x[tree*NPT + i];
        __syncthreads();

        float accll = 0.f;   // log2 units

        // per-node tail: half-domain horizontal combine, 2 converts total
        #define NODE_TAIL(MU, A0, A1, A2_, A3_, BV0, BV1, BV2, BV3, SS)       \
            __half2 t01 = __hadd2(__lows2half2(A0, A1), __highs2half2(A0, A1)); \
            __half2 t23 = __hadd2(__lows2half2(A2_, A3_), __highs2half2(A2_, A3_)); \
            const uint2 eu = *(const uint2*)(sEh + (MU)*256 + rowoff + 4*pblk); \
            float2 f01 = __half22float2(__hmul2(u2h(eu.x), t01));             \
            float2 f23 = __half22float2(__hmul2(u2h(eu.y), t23));             \
            float BV0 = f01.x, BV1 = f01.y, BV2 = f23.x, BV3 = f23.y;         \
            float SS = (BV0 + BV1) + (BV2 + BV3);                             \
            SS += __shfl_xor_sync(0xffffffffu, SS, 1);                        \
            SS += __shfl_xor_sync(0xffffffffu, SS, 2);

        // ====== SUBTREE ng: levels 6..2, barrier-free (quad-local rows) ======

        // ---- Level 6 (leaves fused): 8 local parents k -> slots sbase+k ----
        for (int k = 0; k < 8; k++) {
            float wo0 = 0.f, wo1 = 0.f, wo2 = 0.f, wo3 = 0.f;
            #pragma unroll
            for (int sel = 0; sel < 2; sel++) {
                const int j  = 2*k + sel;                   // local L6 node 0..15
                const int lf = 127 + 32*ng + 2*j;
                const int m0 = sx[lf], m1 = sx[lf + 1];
                const int mu = sx[63 + 16*ng + j];
                const uint4* b0 = (const uint4*)(sPBh + m0*256 + rowoff);
                const uint4* b1 = (const uint4*)(sPBh + m1*256 + rowoff);
                uint4 qa0 = b0[0], qa1 = b0[1];
                uint4 qb0 = b1[0], qb1 = b1[1];
                unsigned ua[8] = {qa0.x,qa0.y,qa0.z,qa0.w, qa1.x,qa1.y,qa1.z,qa1.w};
                unsigned ub[8] = {qb0.x,qb0.y,qb0.z,qb0.w, qb1.x,qb1.y,qb1.z,qb1.w};
                __half2 a0 = __float2half2_rn(0.f), a1 = a0, a2 = a0, a3 = a0;
                #pragma unroll
                for (int c2 = 0; c2 < 8; c2++) {
                    __half2 w2 = __hadd2(u2h(ua[c2]), u2h(ub[c2]));  // leaf pairsum
                    a0 = __hfma2(u2h(A2h[0][c2]), w2, a0);
                    a1 = __hfma2(u2h(A2h[1][c2]), w2, a1);
                    a2 = __hfma2(u2h(A2h[2][c2]), w2, a2);
                    a3 = __hfma2(u2h(A2h[3][c2]), w2, a3);
                }
                accll += 0.25f * (sNuL[m0*NG + g] + sNuL[m1*NG + g]);  // leaf lls

                NODE_TAIL(mu, a0, a1, a2, a3, bv0, bv1, bv2, bv3, s)
                float rs = __fdividef(1.f, s);
                wo0 += bv0*rs; wo1 += bv1*rs; wo2 += bv2*rs; wo3 += bv3*rs;
                accll += 0.25f * (__log2f(s) + sNuL[mu*NG + g]);
            }
            uint2 st;
            st.x = h2u(__floats2half2_rn(wo0, wo1));
            st.y = h2u(__floats2half2_rn(wo2, wo3));
            *(uint2*)(sWh + (sbase + k)*256 + rowoff + 4*pblk) = st;
        }
        __syncwarp();

        // ---- Levels 5..3 (in-place, stride doubling, local to subtree) ----
        #pragma unroll 1
        for (int l = 5; l >= 3; l--) {
            const int nParL = 1 << (l - 3);          // 4, 2, 1
            const int st    = 1 << (5 - l);          // 1, 2, 4
            const int nbase = (1 << l) - 1 + (1 << (l - 2))*ng;
            for (int k = 0; k < nParL; k++) {
                float wo0 = 0.f, wo1 = 0.f, wo2 = 0.f, wo3 = 0.f;
                #pragma unroll
                for (int sel = 0; sel < 2; sel++) {
                    const int j = 2*k + sel;
                    const int mu = sx[nbase + j];
                    const uint4* wp = (const uint4*)(sWh + (sbase + j*st)*256 + rowoff);
                    uint4 q0 = wp[0], q1 = wp[1];
                    unsigned uw[8] = {q0.x,q0.y,q0.z,q0.w, q1.x,q1.y,q1.z,q1.w};
                    __half2 a0 = __float2half2_rn(0.f), a1 = a0, a2 = a0, a3 = a0;
                    #pragma unroll
                    for (int c2 = 0; c2 < 8; c2++) {
                        __half2 w2 = u2h(uw[c2]);    // pre-summed sibling pair
                        a0 = __hfma2(u2h(A2h[0][c2]), w2, a0);
                        a1 = __hfma2(u2h(A2h[1][c2]), w2, a1);
                        a2 = __hfma2(u2h(A2h[2][c2]), w2, a2);
                        a3 = __hfma2(u2h(A2h[3][c2]), w2, a3);
                    }
                    NODE_TAIL(mu, a0, a1, a2, a3, bv0, bv1, bv2, bv3, s)
                    // true nu = s*nu(mu)/2; cancels in normalization;
                    // -1 folded at end, +log2 nu(mu) here
                    float rs = __fdividef(1.f, s);
                    wo0 += bv0*rs; wo1 += bv1*rs; wo2 += bv2*rs; wo3 += bv3*rs;
                    accll += 0.25f * (__log2f(s) + sNuL[mu*NG + g]);
                }
                uint2 stv;
                stv.x = h2u(__floats2half2_rn(wo0, wo1));
                stv.y = h2u(__floats2half2_rn(wo2, wo3));
                *(uint2*)(sWh + (sbase + 2*k*st)*256 + rowoff + 4*pblk) = stv;
            }
            __syncwarp();
        }

        // ---- L2 node (one per subtree): normalized beta -> slot sbase+1 ----
        {
            const int mu = sx[3 + ng];
            const uint4* wp = (const uint4*)(sWh + sbase*256 + rowoff);  // L3 pairsum
            uint4 q0 = wp[0], q1 = wp[1];
            unsigned uw[8] = {q0.x,q0.y,q0.z,q0.w, q1.x,q1.y,q1.z,q1.w};
            __half2 a0 = __float2half2_rn(0.f), a1 = a0, a2 = a0, a3 = a0;
            #pragma unroll
            for (int c2 = 0; c2 < 8; c2++) {
                __half2 w2 = u2h(uw[c2]);
                a0 = __hfma2(u2h(A2h[0][c2]), w2, a0);
                a1 = __hfma2(u2h(A2h[1][c2]), w2, a1);
                a2 = __hfma2(u2h(A2h[2][c2]), w2, a2);
                a3 = __hfma2(u2h(A2h[3][c2]), w2, a3);
            }
            NODE_TAIL(mu, a0, a1, a2, a3, bv0, bv1, bv2, bv3, s)
            float rs = __fdividef(1.f, s);
            uint2 stv;
            stv.x = h2u(__floats2half2_rn(bv0*rs, bv1*rs));
            stv.y = h2u(__floats2half2_rn(bv2*rs, bv3*rs));
            *(uint2*)(sWh + (sbase + 1)*256 + rowoff + 4*pblk) = stv;
            accll += 0.25f * (__log2f(s) + sNuL[mu*NG + g]);
        }

        __syncthreads();   // L2 betas of all 4 subtrees visible

        // ---- L1 + root: ng0 only ----
        if (ng == 0) {
            float wo0 = 0.f, wo1 = 0.f, wo2 = 0.f, wo3 = 0.f;
            #pragma unroll
            for (int sel = 0; sel < 2; sel++) {
                const int mu = sx[1 + sel];
                const uint4* r0 = (const uint4*)(sWh + (2*sel*8 + 1)*256 + rowoff);
                const uint4* r1 = (const uint4*)(sWh + ((2*sel+1)*8 + 1)*256 + rowoff);
                uint4 qa0 = r0[0], qa1 = r0[1];
                uint4 qb0 = r1[0], qb1 = r1[1];
                unsigned ua[8] = {qa0.x,qa0.y,qa0.z,qa0.w, qa1.x,qa1.y,qa1.z,qa1.w};
                unsigned ub[8] = {qb0.x,qb0.y,qb0.z,qb0.w, qb1.x,qb1.y,qb1.z,qb1.w};
                __half2 a0 = __float2half2_rn(0.f), a1 = a0, a2 = a0, a3 = a0;
                #pragma unroll
                for (int c2 = 0; c2 < 8; c2++) {
                    __half2 w2 = __hadd2(u2h(ua[c2]), u2h(ub[c2]));  // L2 pairsum
                    a0 = __hfma2(u2h(A2h[0][c2]), w2, a0);
                    a1 = __hfma2(u2h(A2h[1][c2]), w2, a1);
                    a2 = __hfma2(u2h(A2h[2][c2]), w2, a2);
                    a3 = __hfma2(u2h(A2h[3][c2]), w2, a3);
                }
                NODE_TAIL(mu, a0, a1, a2, a3, bv0, bv1, bv2, bv3, s)
                float rs = __fdividef(1.f, s);
                wo0 += bv0*rs; wo1 += bv1*rs; wo2 += bv2*rs; wo3 += bv3*rs;
                accll += 0.25f * (__log2f(s) + sNuL[mu*NG + g]);
            }
            uint2 stv;
            stv.x = h2u(__floats2half2_rn(wo0, wo1));
            stv.y = h2u(__floats2half2_rn(wo2, wo3));
            *(uint2*)(sWh + 2*256 + rowoff + 4*pblk) = stv;
            __syncwarp();
            const int mu = sx[0];
            const uint4* wp = (const uint4*)(sWh + 2*256 + rowoff);
            uint4 q0 = wp[0], q1 = wp[1];
            unsigned uw[8] = {q0.x,q0.y,q0.z,q0.w, q1.x,q1.y,q1.z,q1.w};
            __half2 a0 = __float2half2_rn(0.f), a1 = a0, a2 = a0, a3 = a0;
            #pragma unroll
            for (int c2 = 0; c2 < 8; c2++) {
                __half2 w2 = u2h(uw[c2]);
                a0 = __hfma2(u2h(A2h[0][c2]), w2, a0);
                a1 = __hfma2(u2h(A2h[1][c2]), w2, a1);
                a2 = __hfma2(u2h(A2h[2][c2]), w2, a2);
                a3 = __hfma2(u2h(A2h[3][c2]), w2, a3);
            }
            NODE_TAIL(mu, a0, a1, a2, a3, bv0, bv1, bv2, bv3, s)
            (void)bv0; (void)bv1; (void)bv2; (void)bv3;
            accll += 0.25f * (__log2f(s) + sNuL[mu*NG + g]);
        }
        #undef NODE_TAIL

        // ---- Deterministic per-g reduction over the 16 threads sharing g ----
        sacc[tid] = accll;
        __syncthreads();
        if (tid < NG) {
            float s = 0.f;
            #pragma unroll
            for (int kk = 0; kk < 16; kk++)
                s += sacc[(kk >> 2)*64 + tid*4 + (kk & 3)];
            // 127 internal nodes owe -1 each in log2 (folded BF=2 mean); to ln
            out[tree*NG + tid] = 0.69314718055994530942f * (s - 127.0f);
        }
    }
}

// ---------------------------------------------------------------------------
extern "C" void kernel_launch(void* const* d_in, const int* in_sizes, int n_in,
                              void* d_out, int out_size) {
    const float* A  = (const float*)d_in[0];
    const float* B  = (const float*)d_in[1];
    const float* Pi = (const float*)d_in[2];
    const int*   x  = (const int*)  d_in[3];
    float* out = (float*)d_out;

    cudaFuncSetAttribute(htmm_upward_kernel,
                         cudaFuncAttributeMaxDynamicSharedMemorySize, DYN_BYTES);

    htmm_softmax_kernel<<<1, 256>>>(A, B, Pi);
    htmm_upward_kernel<<<PGRID, 256, DYN_BYTES>>>(x, out);
}